// round 16
// baseline (speedup 1.0000x reference)
#include <cuda_runtime.h>
#include <cuda_bf16.h>
#include <cstdint>

// Problem constants (fixed by the dataset).
#define BSZ     16
#define DIM     4096
#define NH      32
#define NKV     8
#define HD      128
#define MSL     4096
#define NSPLIT  32
#define SCHUNK  128          // MSL / NSPLIT
#define KVROW   (NKV * HD)   // 1024 floats per cache position
#define SCALE   0.08838834764831845f   // 1/sqrt(128)
#define NROWS   6144         // 4096 q + 1024 k + 1024 v

// ---------------------------------------------------------------------------
// Scratch
// ---------------------------------------------------------------------------
__device__ __align__(16) float g_q[BSZ * NH * HD];
__device__ __align__(16) float g_k[BSZ * NKV * HD];
__device__ __align__(16) float g_v[BSZ * NKV * HD];
__device__ __align__(16) float g_p [2 * NROWS * BSZ];
__device__ __align__(16) float g_po[2 * DIM   * BSZ];
__device__ __align__(16) float g_op[BSZ * NKV * NSPLIT * 4 * HD];   // 8 MB
__device__ float g_m[BSZ * NKV * NSPLIT * 4];
__device__ float g_l[BSZ * NKV * NSPLIT * 4];
__device__ __align__(16) float g_attn[BSZ * DIM];

__device__ __forceinline__ int load_sp(const int* p) {
    int v = *p;
    if (v < 0 || v >= 1000000) v = (int)__int_as_float(v);
    return v;
}

typedef unsigned long long ull;

__device__ __forceinline__ ull ffma2(ull a, ull b, ull c) {
    ull d;
    asm("fma.rn.f32x2 %0, %1, %2, %3;" : "=l"(d) : "l"(a), "l"(b), "l"(c));
    return d;
}
__device__ __forceinline__ float ull_lo(ull v) {
    return __uint_as_float((unsigned)(v & 0xffffffffull));
}
__device__ __forceinline__ float ull_hi(ull v) {
    return __uint_as_float((unsigned)(v >> 32));
}
__device__ __forceinline__ float hsum2(ull v) { return ull_lo(v) + ull_hi(v); }

// Joint 4-head dot + 9-shuffle reduce; returns head-(lane&3) total in every lane.
__device__ __forceinline__ float dot4r(const float4 k4, const float4 ql[4], int lane)
{
    float d0 = k4.x*ql[0].x + k4.y*ql[0].y + k4.z*ql[0].z + k4.w*ql[0].w;
    float d1 = k4.x*ql[1].x + k4.y*ql[1].y + k4.z*ql[1].z + k4.w*ql[1].w;
    float d2 = k4.x*ql[2].x + k4.y*ql[2].y + k4.z*ql[2].z + k4.w*ql[2].w;
    float d3 = k4.x*ql[3].x + k4.y*ql[3].y + k4.z*ql[3].z + k4.w*ql[3].w;
    d0 += __shfl_xor_sync(0xffffffffu, d0, 1);
    d1 += __shfl_xor_sync(0xffffffffu, d1, 1);
    d2 += __shfl_xor_sync(0xffffffffu, d2, 1);
    d3 += __shfl_xor_sync(0xffffffffu, d3, 1);
    float aa = (lane & 1) ? d1 : d0;
    float bb = (lane & 1) ? d3 : d2;
    aa += __shfl_xor_sync(0xffffffffu, aa, 2);
    bb += __shfl_xor_sync(0xffffffffu, bb, 2);
    float cc = (lane & 2) ? bb : aa;
    cc += __shfl_xor_sync(0xffffffffu, cc, 4);
    cc += __shfl_xor_sync(0xffffffffu, cc, 8);
    cc += __shfl_xor_sync(0xffffffffu, cc, 16);
    return cc;
}

// ---------------------------------------------------------------------------
// Kernel 1: QKV GEMV (unchanged).
// ---------------------------------------------------------------------------
__global__ void __launch_bounds__(256, 3) k_gemv_qkv(
    const float* __restrict__ x,
    const float* __restrict__ wq,
    const float* __restrict__ wk,
    const float* __restrict__ wv)
{
    const int warp = threadIdx.x >> 5;
    const int lane = threadIdx.x & 31;
    const int cs   = blockIdx.x & 1;
    const int bh   = (blockIdx.x >> 1) & 1;
    const int rb   = blockIdx.x >> 2;
    const int r0   = rb * 16 + warp * 2;
    const int b0   = bh * 8;
    const int c0   = cs * 2048;

    const float* W; int rbase;
    if (r0 < 4096)      { W = wq; rbase = r0;        }
    else if (r0 < 5120) { W = wk; rbase = r0 - 4096; }
    else                { W = wv; rbase = r0 - 5120; }

    const float* w0p = W + (size_t)(rbase + 0) * DIM + c0;
    const float* w1p = W + (size_t)(rbase + 1) * DIM + c0;
    const float* xp  = x + (size_t)b0 * DIM + c0;

    ull acc[2][8];
#pragma unroll
    for (int r = 0; r < 2; r++)
#pragma unroll
        for (int b = 0; b < 8; b++) acc[r][b] = 0ull;

    const int off = lane * 4;
    for (int c = 0; c < 2048; c += 256) {
        const ulonglong2 w0a = *reinterpret_cast<const ulonglong2*>(w0p + c + off);
        const ulonglong2 w1a = *reinterpret_cast<const ulonglong2*>(w1p + c + off);
        const ulonglong2 w0b = *reinterpret_cast<const ulonglong2*>(w0p + c + 128 + off);
        const ulonglong2 w1b = *reinterpret_cast<const ulonglong2*>(w1p + c + 128 + off);
#pragma unroll
        for (int b = 0; b < 8; b++) {
            const ulonglong2 xa =
                *reinterpret_cast<const ulonglong2*>(xp + (size_t)b * DIM + c + off);
            const ulonglong2 xb =
                *reinterpret_cast<const ulonglong2*>(xp + (size_t)b * DIM + c + 128 + off);
            acc[0][b] = ffma2(w0a.x, xa.x, acc[0][b]);
            acc[0][b] = ffma2(w0a.y, xa.y, acc[0][b]);
            acc[1][b] = ffma2(w1a.x, xa.x, acc[1][b]);
            acc[1][b] = ffma2(w1a.y, xa.y, acc[1][b]);
            acc[0][b] = ffma2(w0b.x, xb.x, acc[0][b]);
            acc[0][b] = ffma2(w0b.y, xb.y, acc[0][b]);
            acc[1][b] = ffma2(w1b.x, xb.x, acc[1][b]);
            acc[1][b] = ffma2(w1b.y, xb.y, acc[1][b]);
        }
    }

#pragma unroll
    for (int r = 0; r < 2; r++) {
        float res = 0.f;
#pragma unroll
        for (int b = 0; b < 8; b++) {
            float v = hsum2(acc[r][b]);
            v += __shfl_xor_sync(0xffffffffu, v, 16);
            v += __shfl_xor_sync(0xffffffffu, v, 8);
            v += __shfl_xor_sync(0xffffffffu, v, 4);
            v += __shfl_xor_sync(0xffffffffu, v, 2);
            v += __shfl_xor_sync(0xffffffffu, v, 1);
            if (lane == b) res = v;
        }
        if (lane < 8)
            g_p[((size_t)cs * NROWS + r0 + r) * BSZ + b0 + lane] = res;
    }
}

// ---------------------------------------------------------------------------
// Kernel 2: combine col-split partials + RoPE (unchanged).
// ---------------------------------------------------------------------------
__global__ void k_fuse(const float* __restrict__ fc, const float* __restrict__ fs)
{
    const int t = blockIdx.x * blockDim.x + threadIdx.x;
    if (t < 32768) {                       // q pairs
        const int b = t >> 11, j = t & 2047;
        const int row = 2 * j;
        const float a  = g_p[(size_t)row * BSZ + b] + g_p[((size_t)NROWS + row) * BSZ + b];
        const float bb = g_p[(size_t)(row + 1) * BSZ + b] + g_p[((size_t)NROWS + row + 1) * BSZ + b];
        const float c = fc[j & 63], s = fs[j & 63];
        g_q[(size_t)b * DIM + row]     = a * c - bb * s;
        g_q[(size_t)b * DIM + row + 1] = a * s + bb * c;
    } else if (t < 40960) {                // k pairs
        const int u = t - 32768;
        const int b = u >> 9, j = u & 511;
        const int row = 4096 + 2 * j;
        const float a  = g_p[(size_t)row * BSZ + b] + g_p[((size_t)NROWS + row) * BSZ + b];
        const float bb = g_p[(size_t)(row + 1) * BSZ + b] + g_p[((size_t)NROWS + row + 1) * BSZ + b];
        const float c = fc[j & 63], s = fs[j & 63];
        g_k[(size_t)b * KVROW + 2 * j]     = a * c - bb * s;
        g_k[(size_t)b * KVROW + 2 * j + 1] = a * s + bb * c;
    } else if (t < 57344) {                // v elements
        const int u = t - 40960;
        const int b = u >> 10, e = u & 1023;
        const int row = 5120 + e;
        g_v[(size_t)b * KVROW + e] =
            g_p[(size_t)row * BSZ + b] + g_p[((size_t)NROWS + row) * BSZ + b];
    }
}

// ---------------------------------------------------------------------------
// Profiling shim: capture = 4th launch (0-based idx 3).  Three noops ahead
// of k_gemv_qkv put the QKV GEMV on the capture slot this round.
// ---------------------------------------------------------------------------
__global__ void k_noop() {}

// ---------------------------------------------------------------------------
// Kernel 3: split-KV attention partials.
// (256,6): regs capped ~42 -> 6 blocks/SM = 75% occ; more loads in flight.
// ---------------------------------------------------------------------------
__global__ void __launch_bounds__(256, 6) k_attn(
    const float* __restrict__ cache_k,
    const float* __restrict__ cache_v,
    const int*   __restrict__ sp_ptr)
{
    const int split = blockIdx.x;
    const int hk    = blockIdx.y;
    const int b     = blockIdx.z;
    const int sp    = load_sp(sp_ptr);
    const int pos0  = split * SCHUNK;
    const int tid   = threadIdx.x;
    const int lane  = tid & 31;
    const int warp  = tid >> 5;
    const bool pure = (pos0 + SCHUNK <= sp);

    __shared__ float  sc[4][SCHUNK];
    __shared__ float4 red4[8][4][32];
    __shared__ float  redm[4][8];
    __shared__ float  redl[4][8];
    __shared__ float  fm[4];

    float4 ql[4];
#pragma unroll
    for (int j = 0; j < 4; j++)
        ql[j] = *reinterpret_cast<const float4*>(
            g_q + (size_t)b * DIM + (hk * 4 + j) * HD + lane * 4);

    // ---- Phase A: scores + running per-head max ----
    const size_t kb = (size_t)b * MSL * KVROW + (size_t)hk * HD;
    float lmax = -1e30f;                       // head = lane & 3
    if (pure) {
        const float* kp = cache_k + kb + (size_t)pos0 * KVROW + lane * 4;
        for (int p = warp; p < SCHUNK; p += 32) {
            const float4 kA = *reinterpret_cast<const float4*>(kp + (size_t)(p     ) * KVROW);
            const float4 kB = *reinterpret_cast<const float4*>(kp + (size_t)(p +  8) * KVROW);
            const float4 kC = *reinterpret_cast<const float4*>(kp + (size_t)(p + 16) * KVROW);
            const float4 kD = *reinterpret_cast<const float4*>(kp + (size_t)(p + 24) * KVROW);
            const float cA = dot4r(kA, ql, lane) * SCALE;
            const float cB = dot4r(kB, ql, lane) * SCALE;
            const float cC = dot4r(kC, ql, lane) * SCALE;
            const float cD = dot4r(kD, ql, lane) * SCALE;
            if (lane < 4) {
                sc[lane][p]      = cA;
                sc[lane][p +  8] = cB;
                sc[lane][p + 16] = cC;
                sc[lane][p + 24] = cD;
            }
            lmax = fmaxf(lmax, fmaxf(fmaxf(cA, cB), fmaxf(cC, cD)));
        }
    } else {
        for (int p = warp; p < SCHUNK; p += 8) {
            const int pos = pos0 + p;
            float4 k4;
            if (pos < sp)
                k4 = *reinterpret_cast<const float4*>(
                    cache_k + kb + (size_t)pos * KVROW + lane * 4);
            else if (pos == sp)
                k4 = *reinterpret_cast<const float4*>(
                    g_k + (b * NKV + hk) * HD + lane * 4);
            else
                k4 = make_float4(0.f, 0.f, 0.f, 0.f);
            const float cc  = dot4r(k4, ql, lane) * SCALE;
            const float val = (pos <= sp) ? cc : -1e30f;
            if (lane < 4) sc[lane][p] = val;
            lmax = fmaxf(lmax, val);
        }
    }
    if (lane < 4) redm[lane][warp] = lmax;
    __syncthreads();
    if (tid < 4) {
        float m = redm[tid][0];
#pragma unroll
        for (int w = 1; w < 8; w++) m = fmaxf(m, redm[tid][w]);
        fm[tid] = m;
    }
    __syncthreads();

    // ---- exp + row-sum ----
    float ll[4] = {0.f, 0.f, 0.f, 0.f};
    for (int p = tid; p < SCHUNK; p += 256) {
#pragma unroll
        for (int h = 0; h < 4; h++) {
            const float e = __expf(sc[h][p] - fm[h]);
            sc[h][p] = e;
            ll[h] += e;
        }
    }
#pragma unroll
    for (int h = 0; h < 4; h++) {
        float v = ll[h];
        v += __shfl_xor_sync(0xffffffffu, v, 16);
        v += __shfl_xor_sync(0xffffffffu, v, 8);
        v += __shfl_xor_sync(0xffffffffu, v, 4);
        v += __shfl_xor_sync(0xffffffffu, v, 2);
        v += __shfl_xor_sync(0xffffffffu, v, 1);
        if (lane == 0) redl[h][warp] = v;
    }
    __syncthreads();

    const size_t pi = (size_t)(b * NKV + hk) * NSPLIT + split;
    if (tid < 4) {
        float s = 0.f;
#pragma unroll
        for (int w = 0; w < 8; w++) s += redl[tid][w];
        g_m[pi * 4 + tid] = fm[tid];
        g_l[pi * 4 + tid] = s;
    }
    __syncthreads();

    // ---- Phase C: V stream ----
    float4 a0 = {0,0,0,0}, a1 = {0,0,0,0}, a2 = {0,0,0,0}, a3 = {0,0,0,0};
    const float* vb = cache_v + (size_t)b * MSL * KVROW + (size_t)hk * HD + lane * 4;
#define ACC4(PP, V4)                                                          \
    {   const float p0 = sc[0][PP], p1 = sc[1][PP],                           \
                    p2 = sc[2][PP], p3 = sc[3][PP];                           \
        a0.x = fmaf(p0, (V4).x, a0.x); a0.y = fmaf(p0, (V4).y, a0.y);         \
        a0.z = fmaf(p0, (V4).z, a0.z); a0.w = fmaf(p0, (V4).w, a0.w);         \
        a1.x = fmaf(p1, (V4).x, a1.x); a1.y = fmaf(p1, (V4).y, a1.y);         \
        a1.z = fmaf(p1, (V4).z, a1.z); a1.w = fmaf(p1, (V4).w, a1.w);         \
        a2.x = fmaf(p2, (V4).x, a2.x); a2.y = fmaf(p2, (V4).y, a2.y);         \
        a2.z = fmaf(p2, (V4).z, a2.z); a2.w = fmaf(p2, (V4).w, a2.w);         \
        a3.x = fmaf(p3, (V4).x, a3.x); a3.y = fmaf(p3, (V4).y, a3.y);         \
        a3.z = fmaf(p3, (V4).z, a3.z); a3.w = fmaf(p3, (V4).w, a3.w); }
    if (pure) {
        const float* vp = vb + (size_t)pos0 * KVROW;
        for (int p = warp; p < SCHUNK; p += 32) {
            const float4 vA = *reinterpret_cast<const float4*>(vp + (size_t)(p     ) * KVROW);
            const float4 vB = *reinterpret_cast<const float4*>(vp + (size_t)(p +  8) * KVROW);
            const float4 vC = *reinterpret_cast<const float4*>(vp + (size_t)(p + 16) * KVROW);
            const float4 vD = *reinterpret_cast<const float4*>(vp + (size_t)(p + 24) * KVROW);
            ACC4(p,      vA);
            ACC4(p +  8, vB);
            ACC4(p + 16, vC);
            ACC4(p + 24, vD);
        }
    } else {
        const float4 gv4 = *reinterpret_cast<const float4*>(
            g_v + (b * NKV + hk) * HD + lane * 4);
        for (int p = warp; p < SCHUNK; p += 8) {
            const int pos = pos0 + p;
            const float4 v4 = (pos == sp) ? gv4
                : *reinterpret_cast<const float4*>(vb + (size_t)pos * KVROW);
            ACC4(p, v4);
        }
    }
#undef ACC4
    red4[warp][0][lane] = a0;
    red4[warp][1][lane] = a1;
    red4[warp][2][lane] = a2;
    red4[warp][3][lane] = a3;
    __syncthreads();

    const float* redf = reinterpret_cast<const float*>(red4);
    float* op = g_op + pi * 4 * HD;
    for (int o = tid; o < 4 * HD; o += 256) {
        float s = 0.f;
#pragma unroll
        for (int w = 0; w < 8; w++) s += redf[w * 512 + o];
        op[o] = s;
    }
}

// ---------------------------------------------------------------------------
// Kernel 4: combine split partials into g_attn (unchanged).
// ---------------------------------------------------------------------------
__global__ void k_combine()
{
    const int bh = blockIdx.x;
    const int d  = threadIdx.x;
    const int b  = bh >> 5, h = bh & 31;
    const int hk = h >> 2, j = h & 3;
    const int base = (b * NKV + hk) * NSPLIT;

    float M = -1e30f;
#pragma unroll
    for (int s = 0; s < NSPLIT; s++) M = fmaxf(M, g_m[(base + s) * 4 + j]);
    float den = 0.f, o = 0.f;
#pragma unroll
    for (int s = 0; s < NSPLIT; s++) {
        const float w = __expf(g_m[(base + s) * 4 + j] - M);
        den += g_l[(base + s) * 4 + j] * w;
        o   += g_op[((size_t)(base + s) * 4 + j) * HD + d] * w;
    }
    g_attn[b * DIM + h * HD + d] = o / den;
}

// ---------------------------------------------------------------------------
// Kernel 5: output GEMV (unchanged).
// ---------------------------------------------------------------------------
__global__ void __launch_bounds__(256, 3) k_gemv_out(
    const float* __restrict__ wo)
{
    const int warp = threadIdx.x >> 5;
    const int lane = threadIdx.x & 31;
    const int cs   = blockIdx.x & 1;
    const int bh   = (blockIdx.x >> 1) & 1;
    const int rb   = blockIdx.x >> 2;
    const int r0   = rb * 16 + warp * 2;
    const int b0   = bh * 8;
    const int c0   = cs * 2048;

    const float* w0p = wo + (size_t)(r0 + 0) * DIM + c0;
    const float* w1p = wo + (size_t)(r0 + 1) * DIM + c0;
    const float* xp  = g_attn + (size_t)b0 * DIM + c0;

    ull acc[2][8];
#pragma unroll
    for (int r = 0; r < 2; r++)
#pragma unroll
        for (int b = 0; b < 8; b++) acc[r][b] = 0ull;

    const int off = lane * 4;
    for (int c = 0; c < 2048; c += 256) {
        const ulonglong2 w0a = *reinterpret_cast<const ulonglong2*>(w0p + c + off);
        const ulonglong2 w1a = *reinterpret_cast<const ulonglong2*>(w1p + c + off);
        const ulonglong2 w0b = *reinterpret_cast<const ulonglong2*>(w0p + c + 128 + off);
        const ulonglong2 w1b = *reinterpret_cast<const ulonglong2*>(w1p + c + 128 + off);
#pragma unroll
        for (int b = 0; b < 8; b++) {
            const ulonglong2 xa =
                *reinterpret_cast<const ulonglong2*>(xp + (size_t)b * DIM + c + off);
            const ulonglong2 xb =
                *reinterpret_cast<const ulonglong2*>(xp + (size_t)b * DIM + c + 128 + off);
            acc[0][b] = ffma2(w0a.x, xa.x, acc[0][b]);
            acc[0][b] = ffma2(w0a.y, xa.y, acc[0][b]);
            acc[1][b] = ffma2(w1a.x, xa.x, acc[1][b]);
            acc[1][b] = ffma2(w1a.y, xa.y, acc[1][b]);
            acc[0][b] = ffma2(w0b.x, xb.x, acc[0][b]);
            acc[0][b] = ffma2(w0b.y, xb.y, acc[0][b]);
            acc[1][b] = ffma2(w1b.x, xb.x, acc[1][b]);
            acc[1][b] = ffma2(w1b.y, xb.y, acc[1][b]);
        }
    }

#pragma unroll
    for (int r = 0; r < 2; r++) {
        float res = 0.f;
#pragma unroll
        for (int b = 0; b < 8; b++) {
            float v = hsum2(acc[r][b]);
            v += __shfl_xor_sync(0xffffffffu, v, 16);
            v += __shfl_xor_sync(0xffffffffu, v, 8);
            v += __shfl_xor_sync(0xffffffffu, v, 4);
            v += __shfl_xor_sync(0xffffffffu, v, 2);
            v += __shfl_xor_sync(0xffffffffu, v, 1);
            if (lane == b) res = v;
        }
        if (lane < 8)
            g_po[((size_t)cs * DIM + r0 + r) * BSZ + b0 + lane] = res;
    }
}

// ---------------------------------------------------------------------------
// Kernel 6: combine output col-split partials -> d_out (unchanged).
// ---------------------------------------------------------------------------
__global__ void k_ocomb(float* __restrict__ out)
{
    const int t = blockIdx.x * blockDim.x + threadIdx.x;
    const int b = t >> 12, row = t & 4095;
    out[(size_t)b * DIM + row] =
        g_po[(size_t)row * BSZ + b] + g_po[((size_t)DIM + row) * BSZ + b];
}

// ---------------------------------------------------------------------------
extern "C" void kernel_launch(void* const* d_in, const int* in_sizes, int n_in,
                              void* d_out, int out_size)
{
    const float* x  = (const float*)d_in[0];
    const float* wq = (const float*)d_in[1];
    const float* wk = (const float*)d_in[2];
    const float* wv = (const float*)d_in[3];
    const float* wo = (const float*)d_in[4];
    const float* ck = (const float*)d_in[5];
    const float* cv = (const float*)d_in[6];
    const float* fc = (const float*)d_in[7];
    const float* fs = (const float*)d_in[8];
    const int*   sp = (const int*)d_in[9];
    float* out = (float*)d_out;

    k_noop<<<1, 32>>>();                    // capture shim: qkv -> launch idx 3
    k_noop<<<1, 32>>>();
    k_noop<<<1, 32>>>();
    k_gemv_qkv<<<1536, 256>>>(x, wq, wk, wv);
    k_fuse<<<224, 256>>>(fc, fs);
    dim3 ag(NSPLIT, NKV, BSZ);
    k_attn<<<ag, 256>>>(ck, cv, sp);
    k_combine<<<BSZ * NH, HD>>>();
    k_gemv_out<<<1024, 256>>>(wo);
    k_ocomb<<<256, 256>>>(out);
}

// round 17
// speedup vs baseline: 1.4951x; 1.4951x over previous
#include <cuda_runtime.h>
#include <cuda_bf16.h>
#include <cstdint>

// Problem constants (fixed by the dataset).
#define BSZ     16
#define DIM     4096
#define NH      32
#define NKV     8
#define HD      128
#define MSL     4096
#define NSPLIT  32
#define SCHUNK  128          // MSL / NSPLIT
#define KVROW   (NKV * HD)   // 1024 floats per cache position
#define SCALE   0.08838834764831845f   // 1/sqrt(128)
#define NROWS   6144         // 4096 q + 1024 k + 1024 v

// ---------------------------------------------------------------------------
// Scratch
// ---------------------------------------------------------------------------
__device__ __align__(16) float g_q[BSZ * NH * HD];
__device__ __align__(16) float g_k[BSZ * NKV * HD];
__device__ __align__(16) float g_v[BSZ * NKV * HD];
__device__ __align__(16) float g_p [2 * NROWS * BSZ];
__device__ __align__(16) float g_po[2 * DIM   * BSZ];
__device__ __align__(16) float g_op[BSZ * NKV * NSPLIT * 4 * HD];   // 8 MB
__device__ float g_m[BSZ * NKV * NSPLIT * 4];
__device__ float g_l[BSZ * NKV * NSPLIT * 4];
__device__ __align__(16) float g_attn[BSZ * DIM];

__device__ __forceinline__ int load_sp(const int* p) {
    int v = *p;
    if (v < 0 || v >= 1000000) v = (int)__int_as_float(v);
    return v;
}

typedef unsigned long long ull;

__device__ __forceinline__ ull ffma2(ull a, ull b, ull c) {
    ull d;
    asm("fma.rn.f32x2 %0, %1, %2, %3;" : "=l"(d) : "l"(a), "l"(b), "l"(c));
    return d;
}
__device__ __forceinline__ float ull_lo(ull v) {
    return __uint_as_float((unsigned)(v & 0xffffffffull));
}
__device__ __forceinline__ float ull_hi(ull v) {
    return __uint_as_float((unsigned)(v >> 32));
}
__device__ __forceinline__ float hsum2(ull v) { return ull_lo(v) + ull_hi(v); }

// Joint 4-head dot + 9-shuffle reduce; returns head-(lane&3) total in every lane.
__device__ __forceinline__ float dot4r(const float4 k4, const float4 ql[4], int lane)
{
    float d0 = k4.x*ql[0].x + k4.y*ql[0].y + k4.z*ql[0].z + k4.w*ql[0].w;
    float d1 = k4.x*ql[1].x + k4.y*ql[1].y + k4.z*ql[1].z + k4.w*ql[1].w;
    float d2 = k4.x*ql[2].x + k4.y*ql[2].y + k4.z*ql[2].z + k4.w*ql[2].w;
    float d3 = k4.x*ql[3].x + k4.y*ql[3].y + k4.z*ql[3].z + k4.w*ql[3].w;
    d0 += __shfl_xor_sync(0xffffffffu, d0, 1);
    d1 += __shfl_xor_sync(0xffffffffu, d1, 1);
    d2 += __shfl_xor_sync(0xffffffffu, d2, 1);
    d3 += __shfl_xor_sync(0xffffffffu, d3, 1);
    float aa = (lane & 1) ? d1 : d0;
    float bb = (lane & 1) ? d3 : d2;
    aa += __shfl_xor_sync(0xffffffffu, aa, 2);
    bb += __shfl_xor_sync(0xffffffffu, bb, 2);
    float cc = (lane & 2) ? bb : aa;
    cc += __shfl_xor_sync(0xffffffffu, cc, 4);
    cc += __shfl_xor_sync(0xffffffffu, cc, 8);
    cc += __shfl_xor_sync(0xffffffffu, cc, 16);
    return cc;
}

// ---------------------------------------------------------------------------
// Kernel 1: QKV GEMV, R=4 row blocking (x-load amortized over 4 rows).
// Warp = 4 rows x 8 batches x 2048 cols.  Block = 32 rows.
// grid = 192 * 4 = 768 blocks, (256,2).
// ---------------------------------------------------------------------------
__global__ void __launch_bounds__(256, 2) k_gemv_qkv(
    const float* __restrict__ x,
    const float* __restrict__ wq,
    const float* __restrict__ wk,
    const float* __restrict__ wv)
{
    const int warp = threadIdx.x >> 5;
    const int lane = threadIdx.x & 31;
    const int cs   = blockIdx.x & 1;
    const int bh   = (blockIdx.x >> 1) & 1;
    const int rb   = blockIdx.x >> 2;
    const int r0   = rb * 32 + warp * 4;
    const int b0   = bh * 8;
    const int c0   = cs * 2048;

    const float* W; int rbase;
    if (r0 < 4096)      { W = wq; rbase = r0;        }
    else if (r0 < 5120) { W = wk; rbase = r0 - 4096; }
    else                { W = wv; rbase = r0 - 5120; }

    const float* w0p = W + (size_t)(rbase + 0) * DIM + c0;
    const float* w1p = W + (size_t)(rbase + 1) * DIM + c0;
    const float* w2p = W + (size_t)(rbase + 2) * DIM + c0;
    const float* w3p = W + (size_t)(rbase + 3) * DIM + c0;
    const float* xp  = x + (size_t)b0 * DIM + c0;

    ull acc[4][8];
#pragma unroll
    for (int r = 0; r < 4; r++)
#pragma unroll
        for (int b = 0; b < 8; b++) acc[r][b] = 0ull;

    const int off = lane * 4;
    for (int c = 0; c < 2048; c += 128) {
        const ulonglong2 w0 = *reinterpret_cast<const ulonglong2*>(w0p + c + off);
        const ulonglong2 w1 = *reinterpret_cast<const ulonglong2*>(w1p + c + off);
        const ulonglong2 w2 = *reinterpret_cast<const ulonglong2*>(w2p + c + off);
        const ulonglong2 w3 = *reinterpret_cast<const ulonglong2*>(w3p + c + off);
#pragma unroll
        for (int b = 0; b < 8; b++) {
            const ulonglong2 xv =
                *reinterpret_cast<const ulonglong2*>(xp + (size_t)b * DIM + c + off);
            acc[0][b] = ffma2(w0.x, xv.x, acc[0][b]);
            acc[0][b] = ffma2(w0.y, xv.y, acc[0][b]);
            acc[1][b] = ffma2(w1.x, xv.x, acc[1][b]);
            acc[1][b] = ffma2(w1.y, xv.y, acc[1][b]);
            acc[2][b] = ffma2(w2.x, xv.x, acc[2][b]);
            acc[2][b] = ffma2(w2.y, xv.y, acc[2][b]);
            acc[3][b] = ffma2(w3.x, xv.x, acc[3][b]);
            acc[3][b] = ffma2(w3.y, xv.y, acc[3][b]);
        }
    }

#pragma unroll
    for (int r = 0; r < 4; r++) {
        float res = 0.f;
#pragma unroll
        for (int b = 0; b < 8; b++) {
            float v = hsum2(acc[r][b]);
            v += __shfl_xor_sync(0xffffffffu, v, 16);
            v += __shfl_xor_sync(0xffffffffu, v, 8);
            v += __shfl_xor_sync(0xffffffffu, v, 4);
            v += __shfl_xor_sync(0xffffffffu, v, 2);
            v += __shfl_xor_sync(0xffffffffu, v, 1);
            if (lane == b) res = v;
        }
        if (lane < 8)
            g_p[((size_t)cs * NROWS + r0 + r) * BSZ + b0 + lane] = res;
    }
}

// ---------------------------------------------------------------------------
// Kernel 2: combine col-split partials + RoPE (unchanged).
// ---------------------------------------------------------------------------
__global__ void k_fuse(const float* __restrict__ fc, const float* __restrict__ fs)
{
    const int t = blockIdx.x * blockDim.x + threadIdx.x;
    if (t < 32768) {                       // q pairs
        const int b = t >> 11, j = t & 2047;
        const int row = 2 * j;
        const float a  = g_p[(size_t)row * BSZ + b] + g_p[((size_t)NROWS + row) * BSZ + b];
        const float bb = g_p[(size_t)(row + 1) * BSZ + b] + g_p[((size_t)NROWS + row + 1) * BSZ + b];
        const float c = fc[j & 63], s = fs[j & 63];
        g_q[(size_t)b * DIM + row]     = a * c - bb * s;
        g_q[(size_t)b * DIM + row + 1] = a * s + bb * c;
    } else if (t < 40960) {                // k pairs
        const int u = t - 32768;
        const int b = u >> 9, j = u & 511;
        const int row = 4096 + 2 * j;
        const float a  = g_p[(size_t)row * BSZ + b] + g_p[((size_t)NROWS + row) * BSZ + b];
        const float bb = g_p[(size_t)(row + 1) * BSZ + b] + g_p[((size_t)NROWS + row + 1) * BSZ + b];
        const float c = fc[j & 63], s = fs[j & 63];
        g_k[(size_t)b * KVROW + 2 * j]     = a * c - bb * s;
        g_k[(size_t)b * KVROW + 2 * j + 1] = a * s + bb * c;
    } else if (t < 57344) {                // v elements
        const int u = t - 40960;
        const int b = u >> 10, e = u & 1023;
        const int row = 5120 + e;
        g_v[(size_t)b * KVROW + e] =
            g_p[(size_t)row * BSZ + b] + g_p[((size_t)NROWS + row) * BSZ + b];
    }
}

// ---------------------------------------------------------------------------
// Profiling shim: capture = 4th launch (idx 3) -> k_gemv_qkv this round.
// ---------------------------------------------------------------------------
__global__ void k_noop() {}

// ---------------------------------------------------------------------------
// Kernel 3: split-KV attention partials.
// REVERTED to plain (256) — the (256,6) cap spilled and cost ~70 us.
// ---------------------------------------------------------------------------
__global__ void __launch_bounds__(256) k_attn(
    const float* __restrict__ cache_k,
    const float* __restrict__ cache_v,
    const int*   __restrict__ sp_ptr)
{
    const int split = blockIdx.x;
    const int hk    = blockIdx.y;
    const int b     = blockIdx.z;
    const int sp    = load_sp(sp_ptr);
    const int pos0  = split * SCHUNK;
    const int tid   = threadIdx.x;
    const int lane  = tid & 31;
    const int warp  = tid >> 5;
    const bool pure = (pos0 + SCHUNK <= sp);

    __shared__ float  sc[4][SCHUNK];
    __shared__ float4 red4[8][4][32];
    __shared__ float  redm[4][8];
    __shared__ float  redl[4][8];
    __shared__ float  fm[4];

    float4 ql[4];
#pragma unroll
    for (int j = 0; j < 4; j++)
        ql[j] = *reinterpret_cast<const float4*>(
            g_q + (size_t)b * DIM + (hk * 4 + j) * HD + lane * 4);

    // ---- Phase A: scores + running per-head max ----
    const size_t kb = (size_t)b * MSL * KVROW + (size_t)hk * HD;
    float lmax = -1e30f;                       // head = lane & 3
    if (pure) {
        const float* kp = cache_k + kb + (size_t)pos0 * KVROW + lane * 4;
        for (int p = warp; p < SCHUNK; p += 32) {
            const float4 kA = *reinterpret_cast<const float4*>(kp + (size_t)(p     ) * KVROW);
            const float4 kB = *reinterpret_cast<const float4*>(kp + (size_t)(p +  8) * KVROW);
            const float4 kC = *reinterpret_cast<const float4*>(kp + (size_t)(p + 16) * KVROW);
            const float4 kD = *reinterpret_cast<const float4*>(kp + (size_t)(p + 24) * KVROW);
            const float cA = dot4r(kA, ql, lane) * SCALE;
            const float cB = dot4r(kB, ql, lane) * SCALE;
            const float cC = dot4r(kC, ql, lane) * SCALE;
            const float cD = dot4r(kD, ql, lane) * SCALE;
            if (lane < 4) {
                sc[lane][p]      = cA;
                sc[lane][p +  8] = cB;
                sc[lane][p + 16] = cC;
                sc[lane][p + 24] = cD;
            }
            lmax = fmaxf(lmax, fmaxf(fmaxf(cA, cB), fmaxf(cC, cD)));
        }
    } else {
        for (int p = warp; p < SCHUNK; p += 8) {
            const int pos = pos0 + p;
            float4 k4;
            if (pos < sp)
                k4 = *reinterpret_cast<const float4*>(
                    cache_k + kb + (size_t)pos * KVROW + lane * 4);
            else if (pos == sp)
                k4 = *reinterpret_cast<const float4*>(
                    g_k + (b * NKV + hk) * HD + lane * 4);
            else
                k4 = make_float4(0.f, 0.f, 0.f, 0.f);
            const float cc  = dot4r(k4, ql, lane) * SCALE;
            const float val = (pos <= sp) ? cc : -1e30f;
            if (lane < 4) sc[lane][p] = val;
            lmax = fmaxf(lmax, val);
        }
    }
    if (lane < 4) redm[lane][warp] = lmax;
    __syncthreads();
    if (tid < 4) {
        float m = redm[tid][0];
#pragma unroll
        for (int w = 1; w < 8; w++) m = fmaxf(m, redm[tid][w]);
        fm[tid] = m;
    }
    __syncthreads();

    // ---- exp + row-sum ----
    float ll[4] = {0.f, 0.f, 0.f, 0.f};
    for (int p = tid; p < SCHUNK; p += 256) {
#pragma unroll
        for (int h = 0; h < 4; h++) {
            const float e = __expf(sc[h][p] - fm[h]);
            sc[h][p] = e;
            ll[h] += e;
        }
    }
#pragma unroll
    for (int h = 0; h < 4; h++) {
        float v = ll[h];
        v += __shfl_xor_sync(0xffffffffu, v, 16);
        v += __shfl_xor_sync(0xffffffffu, v, 8);
        v += __shfl_xor_sync(0xffffffffu, v, 4);
        v += __shfl_xor_sync(0xffffffffu, v, 2);
        v += __shfl_xor_sync(0xffffffffu, v, 1);
        if (lane == 0) redl[h][warp] = v;
    }
    __syncthreads();

    const size_t pi = (size_t)(b * NKV + hk) * NSPLIT + split;
    if (tid < 4) {
        float s = 0.f;
#pragma unroll
        for (int w = 0; w < 8; w++) s += redl[tid][w];
        g_m[pi * 4 + tid] = fm[tid];
        g_l[pi * 4 + tid] = s;
    }
    __syncthreads();

    // ---- Phase C: V stream ----
    float4 a0 = {0,0,0,0}, a1 = {0,0,0,0}, a2 = {0,0,0,0}, a3 = {0,0,0,0};
    const float* vb = cache_v + (size_t)b * MSL * KVROW + (size_t)hk * HD + lane * 4;
#define ACC4(PP, V4)                                                          \
    {   const float p0 = sc[0][PP], p1 = sc[1][PP],                           \
                    p2 = sc[2][PP], p3 = sc[3][PP];                           \
        a0.x = fmaf(p0, (V4).x, a0.x); a0.y = fmaf(p0, (V4).y, a0.y);         \
        a0.z = fmaf(p0, (V4).z, a0.z); a0.w = fmaf(p0, (V4).w, a0.w);         \
        a1.x = fmaf(p1, (V4).x, a1.x); a1.y = fmaf(p1, (V4).y, a1.y);         \
        a1.z = fmaf(p1, (V4).z, a1.z); a1.w = fmaf(p1, (V4).w, a1.w);         \
        a2.x = fmaf(p2, (V4).x, a2.x); a2.y = fmaf(p2, (V4).y, a2.y);         \
        a2.z = fmaf(p2, (V4).z, a2.z); a2.w = fmaf(p2, (V4).w, a2.w);         \
        a3.x = fmaf(p3, (V4).x, a3.x); a3.y = fmaf(p3, (V4).y, a3.y);         \
        a3.z = fmaf(p3, (V4).z, a3.z); a3.w = fmaf(p3, (V4).w, a3.w); }
    if (pure) {
        const float* vp = vb + (size_t)pos0 * KVROW;
        for (int p = warp; p < SCHUNK; p += 32) {
            const float4 vA = *reinterpret_cast<const float4*>(vp + (size_t)(p     ) * KVROW);
            const float4 vB = *reinterpret_cast<const float4*>(vp + (size_t)(p +  8) * KVROW);
            const float4 vC = *reinterpret_cast<const float4*>(vp + (size_t)(p + 16) * KVROW);
            const float4 vD = *reinterpret_cast<const float4*>(vp + (size_t)(p + 24) * KVROW);
            ACC4(p,      vA);
            ACC4(p +  8, vB);
            ACC4(p + 16, vC);
            ACC4(p + 24, vD);
        }
    } else {
        const float4 gv4 = *reinterpret_cast<const float4*>(
            g_v + (b * NKV + hk) * HD + lane * 4);
        for (int p = warp; p < SCHUNK; p += 8) {
            const int pos = pos0 + p;
            const float4 v4 = (pos == sp) ? gv4
                : *reinterpret_cast<const float4*>(vb + (size_t)pos * KVROW);
            ACC4(p, v4);
        }
    }
#undef ACC4
    red4[warp][0][lane] = a0;
    red4[warp][1][lane] = a1;
    red4[warp][2][lane] = a2;
    red4[warp][3][lane] = a3;
    __syncthreads();

    const float* redf = reinterpret_cast<const float*>(red4);
    float* op = g_op + pi * 4 * HD;
    for (int o = tid; o < 4 * HD; o += 256) {
        float s = 0.f;
#pragma unroll
        for (int w = 0; w < 8; w++) s += redf[w * 512 + o];
        op[o] = s;
    }
}

// ---------------------------------------------------------------------------
// Kernel 4: combine split partials into g_attn (unchanged).
// ---------------------------------------------------------------------------
__global__ void k_combine()
{
    const int bh = blockIdx.x;
    const int d  = threadIdx.x;
    const int b  = bh >> 5, h = bh & 31;
    const int hk = h >> 2, j = h & 3;
    const int base = (b * NKV + hk) * NSPLIT;

    float M = -1e30f;
#pragma unroll
    for (int s = 0; s < NSPLIT; s++) M = fmaxf(M, g_m[(base + s) * 4 + j]);
    float den = 0.f, o = 0.f;
#pragma unroll
    for (int s = 0; s < NSPLIT; s++) {
        const float w = __expf(g_m[(base + s) * 4 + j] - M);
        den += g_l[(base + s) * 4 + j] * w;
        o   += g_op[((size_t)(base + s) * 4 + j) * HD + d] * w;
    }
    g_attn[b * DIM + h * HD + d] = o / den;
}

// ---------------------------------------------------------------------------
// Kernel 5: output GEMV, R=4 row blocking (same scheme as kernel 1).
// grid = 128 * 4 = 512 blocks, (256,2).
// ---------------------------------------------------------------------------
__global__ void __launch_bounds__(256, 2) k_gemv_out(
    const float* __restrict__ wo)
{
    const int warp = threadIdx.x >> 5;
    const int lane = threadIdx.x & 31;
    const int cs   = blockIdx.x & 1;
    const int bh   = (blockIdx.x >> 1) & 1;
    const int rb   = blockIdx.x >> 2;
    const int r0   = rb * 32 + warp * 4;
    const int b0   = bh * 8;
    const int c0   = cs * 2048;

    const float* w0p = wo + (size_t)(r0 + 0) * DIM + c0;
    const float* w1p = wo + (size_t)(r0 + 1) * DIM + c0;
    const float* w2p = wo + (size_t)(r0 + 2) * DIM + c0;
    const float* w3p = wo + (size_t)(r0 + 3) * DIM + c0;
    const float* xp  = g_attn + (size_t)b0 * DIM + c0;

    ull acc[4][8];
#pragma unroll
    for (int r = 0; r < 4; r++)
#pragma unroll
        for (int b = 0; b < 8; b++) acc[r][b] = 0ull;

    const int off = lane * 4;
    for (int c = 0; c < 2048; c += 128) {
        const ulonglong2 w0 = *reinterpret_cast<const ulonglong2*>(w0p + c + off);
        const ulonglong2 w1 = *reinterpret_cast<const ulonglong2*>(w1p + c + off);
        const ulonglong2 w2 = *reinterpret_cast<const ulonglong2*>(w2p + c + off);
        const ulonglong2 w3 = *reinterpret_cast<const ulonglong2*>(w3p + c + off);
#pragma unroll
        for (int b = 0; b < 8; b++) {
            const ulonglong2 xv =
                *reinterpret_cast<const ulonglong2*>(xp + (size_t)b * DIM + c + off);
            acc[0][b] = ffma2(w0.x, xv.x, acc[0][b]);
            acc[0][b] = ffma2(w0.y, xv.y, acc[0][b]);
            acc[1][b] = ffma2(w1.x, xv.x, acc[1][b]);
            acc[1][b] = ffma2(w1.y, xv.y, acc[1][b]);
            acc[2][b] = ffma2(w2.x, xv.x, acc[2][b]);
            acc[2][b] = ffma2(w2.y, xv.y, acc[2][b]);
            acc[3][b] = ffma2(w3.x, xv.x, acc[3][b]);
            acc[3][b] = ffma2(w3.y, xv.y, acc[3][b]);
        }
    }

#pragma unroll
    for (int r = 0; r < 4; r++) {
        float res = 0.f;
#pragma unroll
        for (int b = 0; b < 8; b++) {
            float v = hsum2(acc[r][b]);
            v += __shfl_xor_sync(0xffffffffu, v, 16);
            v += __shfl_xor_sync(0xffffffffu, v, 8);
            v += __shfl_xor_sync(0xffffffffu, v, 4);
            v += __shfl_xor_sync(0xffffffffu, v, 2);
            v += __shfl_xor_sync(0xffffffffu, v, 1);
            if (lane == b) res = v;
        }
        if (lane < 8)
            g_po[((size_t)cs * DIM + r0 + r) * BSZ + b0 + lane] = res;
    }
}

// ---------------------------------------------------------------------------
// Kernel 6: combine output col-split partials -> d_out (unchanged).
// ---------------------------------------------------------------------------
__global__ void k_ocomb(float* __restrict__ out)
{
    const int t = blockIdx.x * blockDim.x + threadIdx.x;
    const int b = t >> 12, row = t & 4095;
    out[(size_t)b * DIM + row] =
        g_po[(size_t)row * BSZ + b] + g_po[((size_t)DIM + row) * BSZ + b];
}

// ---------------------------------------------------------------------------
extern "C" void kernel_launch(void* const* d_in, const int* in_sizes, int n_in,
                              void* d_out, int out_size)
{
    const float* x  = (const float*)d_in[0];
    const float* wq = (const float*)d_in[1];
    const float* wk = (const float*)d_in[2];
    const float* wv = (const float*)d_in[3];
    const float* wo = (const float*)d_in[4];
    const float* ck = (const float*)d_in[5];
    const float* cv = (const float*)d_in[6];
    const float* fc = (const float*)d_in[7];
    const float* fs = (const float*)d_in[8];
    const int*   sp = (const int*)d_in[9];
    float* out = (float*)d_out;

    k_noop<<<1, 32>>>();                    // capture shim: qkv -> launch idx 3
    k_noop<<<1, 32>>>();
    k_noop<<<1, 32>>>();
    k_gemv_qkv<<<768, 256>>>(x, wq, wk, wv);
    k_fuse<<<224, 256>>>(fc, fs);
    dim3 ag(NSPLIT, NKV, BSZ);
    k_attn<<<ag, 256>>>(ck, cv, sp);
    k_combine<<<BSZ * NH, HD>>>();
    k_gemv_out<<<512, 256>>>(wo);
    k_ocomb<<<256, 256>>>(out);
}